// round 4
// baseline (speedup 1.0000x reference)
#include <cuda_runtime.h>
#include <cuda_bf16.h>
#include <cstdint>
#include <cfloat>

#define VOCAB   500000
#define EMB_D   128
#define HID     128
#define STEPS   64

// ---------------- device globals (scratch; no allocation allowed) ----------
__device__ float               g_cs[STEPS * HID];    // cell states [step][k]
__device__ uint4               g_bfrag[2048];        // prepacked B frags [nc][kc][lane]
__device__ unsigned long long  g_best[STEPS];        // (enc(score)<<32)|~idx
__device__ int                 g_done = 0;           // last-CTA counter (self-reset)

// ---------------- helpers ---------------------------------------------------
__device__ __forceinline__ uint32_t enc_f32(float f) {
    uint32_t u = __float_as_uint(f);
    return (u & 0x80000000u) ? ~u : (u | 0x80000000u);
}
__device__ __forceinline__ uint32_t smem_u32(const void* p) {
    return (uint32_t)__cvta_generic_to_shared(p);
}
__device__ __forceinline__ void st_cluster_f32(float* p, uint32_t rank, float v) {
    uint32_t a = smem_u32(p), r;
    asm volatile("mapa.shared::cluster.u32 %0, %1, %2;" : "=r"(r) : "r"(a), "r"(rank));
    asm volatile("st.shared::cluster.f32 [%0], %1;" :: "r"(r), "f"(v) : "memory");
}
__device__ __forceinline__ void arrive_cluster(uint32_t bar_local, uint32_t rank) {
    uint32_t r;
    asm volatile("mapa.shared::cluster.u32 %0, %1, %2;" : "=r"(r) : "r"(bar_local), "r"(rank));
    asm volatile("mbarrier.arrive.release.cluster.shared::cluster.b64 _, [%0];"
                 :: "r"(r) : "memory");
}
#define WAIT_PARITY_CLUSTER(mbar, par) do {                                    \
    uint32_t _d;                                                               \
    do {                                                                       \
        asm volatile("{\n\t.reg .pred p;\n\t"                                  \
            "mbarrier.try_wait.parity.acquire.cluster.shared::cta.b64 p, [%1], %2, 0x989680;\n\t" \
            "selp.b32 %0, 1, 0, p;\n\t}"                                       \
            : "=r"(_d) : "r"(mbar), "r"(par) : "memory");                      \
    } while (!_d); } while (0)
#define MBAR_INIT(mbar, cnt) \
    asm volatile("mbarrier.init.shared.b64 [%0], %1;" :: "r"(mbar), "r"(cnt) : "memory")

__device__ __forceinline__ uint32_t my_cluster_rank() {
    uint32_t r; asm("mov.u32 %0, %%cluster_ctarank;" : "=r"(r)); return r;
}
__device__ __forceinline__ void cluster_sync_all() {
    asm volatile("barrier.cluster.arrive.aligned;" ::: "memory");
    asm volatile("barrier.cluster.wait.aligned;"   ::: "memory");
}
__device__ __forceinline__ float sigf(float x) { return 1.0f / (1.0f + expf(-x)); }

// split a float2 into bf16x2 hi and bf16x2 lo(residual); low halves = .x
__device__ __forceinline__ void split2(float2 v, uint32_t& hi, uint32_t& lo) {
    __nv_bfloat162 h = __floats2bfloat162_rn(v.x, v.y);
    hi = *(uint32_t*)&h;
    float rx = v.x - __bfloat162float(h.x);
    float ry = v.y - __bfloat162float(h.y);
    __nv_bfloat162 l = __floats2bfloat162_rn(rx, ry);
    lo = *(uint32_t*)&l;
}

// m16n8k16 row.col f32.bf16.bf16.f32
__device__ __forceinline__ void mma16816(float* c, const uint32_t* a,
                                         uint32_t b0, uint32_t b1) {
    asm volatile(
        "mma.sync.aligned.m16n8k16.row.col.f32.bf16.bf16.f32 "
        "{%0,%1,%2,%3}, {%4,%5,%6,%7}, {%8,%9}, {%0,%1,%2,%3};"
        : "+f"(c[0]), "+f"(c[1]), "+f"(c[2]), "+f"(c[3])
        : "r"(a[0]), "r"(a[1]), "r"(a[2]), "r"(a[3]), "r"(b0), "r"(b1));
}

// ============================================================================
// K1: 64 LSTM steps (cluster of 8 CTAs x 256 threads), mbarrier state exchange
// ============================================================================
__global__ void __launch_bounds__(256, 1)
k1_lstm(const float* __restrict__ embed,
        const float* __restrict__ w_ih,
        const float* __restrict__ w_hh,
        const float* __restrict__ inp,
        const float* __restrict__ b_ih,
        const float* __restrict__ b_hh,
        float* __restrict__ out, int write_cs) {
    __shared__ float xh[2][256];
    __shared__ float gates_sm[64];
    __shared__ float Ksm[64];
    __shared__ float inp_sm[128];
    __shared__ alignas(8) unsigned long long barr[2];

    const int tid  = threadIdx.x;
    const uint32_t rank = my_cluster_rank();
    const uint32_t bar0 = smem_u32(&barr[0]);
    const uint32_t bar1 = smem_u32(&barr[1]);

    const int lr   = tid >> 2;          // local gate row 0..63
    const int part = tid & 3;           // column quarter
    const int g    = lr >> 4;           // gate 0..3
    const int jj   = lr & 15;           // local hidden idx
    const int j    = (int)rank * 16 + jj;
    const int grow = g * 128 + j;       // global gate row

    if (rank == 0 && tid < STEPS) g_best[tid] = 0ull;

    if (tid == 0) { MBAR_INIT(bar0, 128); MBAR_INIT(bar1, 128); }
    if (tid < 128) {
        inp_sm[tid]      = inp[tid];
        xh[0][tid]       = embed[tid];
        xh[0][128 + tid] = 0.f;
    }

    float w[64];
    #pragma unroll
    for (int cc = 0; cc < 64; ++cc) {
        int col = part * 64 + cc;
        w[cc] = (col < 128) ? w_ih[grow * 256 + col]
                            : w_hh[grow * 128 + (col - 128)];
    }
    __syncthreads();
    cluster_sync_all();   // all barriers initialized before any arrive

    // fold K[grow] = b_ih + b_hh + W_ih[:,128:] @ inp
    {
        const float* wr = w_ih + grow * 256 + 128 + part * 32;
        float s = 0.f;
        #pragma unroll 8
        for (int c = 0; c < 32; ++c) s = fmaf(wr[c], inp_sm[part * 32 + c], s);
        s += __shfl_xor_sync(0xffffffffu, s, 1);
        s += __shfl_xor_sync(0xffffffffu, s, 2);
        if (part == 0) Ksm[lr] = s + b_ih[grow] + b_hh[grow];
    }
    __syncthreads();

    float c_reg = 0.f, k0v = 0.f, k1v = 0.f, k2v = 0.f, k3v = 0.f;
    if (tid < 16) {
        k0v = Ksm[ 0 + tid]; k1v = Ksm[16 + tid];
        k2v = Ksm[32 + tid]; k3v = Ksm[48 + tid];
    }
    __syncthreads();

    int cnt0 = 0, cnt1 = 0;
    for (int step = 0; step < STEPS; ++step) {
        if (step > 0) {
            if (step & 1) { WAIT_PARITY_CLUSTER(bar1, cnt1 & 1); ++cnt1; }
            else          { WAIT_PARITY_CLUSTER(bar0, cnt0 & 1); ++cnt0; }
        }
        const int p = step & 1;
        const float4* xv = (const float4*)&xh[p][part * 64];
        float a0 = 0.f, a1 = 0.f, a2 = 0.f, a3 = 0.f;
        #pragma unroll
        for (int q = 0; q < 16; ++q) {
            float4 v = xv[q];
            a0 = fmaf(w[4*q + 0], v.x, a0);
            a1 = fmaf(w[4*q + 1], v.y, a1);
            a2 = fmaf(w[4*q + 2], v.z, a2);
            a3 = fmaf(w[4*q + 3], v.w, a3);
        }
        float acc = (a0 + a1) + (a2 + a3);
        acc += __shfl_xor_sync(0xffffffffu, acc, 1);
        acc += __shfl_xor_sync(0xffffffffu, acc, 2);
        if (part == 0) gates_sm[lr] = acc;
        __syncthreads();   // all reads of xh[p] complete before epilogue arrives

        if (tid < 16) {
            int je = (int)rank * 16 + tid;
            float gi = gates_sm[ 0 + tid] + k0v;
            float gf = gates_sm[16 + tid] + k1v;
            float gg = gates_sm[32 + tid] + k2v;
            float go = gates_sm[48 + tid] + k3v;
            float iv = sigf(gi), fv = sigf(gf), gv = tanhf(gg), ov = sigf(go);
            float c_new = fv * c_reg + iv * gv;
            float h_new = ov * tanhf(c_new);
            c_reg = c_new;
            if (write_cs) out[step * 128 + je] = c_new;
            g_cs[step * 128 + je] = c_new;
            if (step < STEPS - 1) {
                const int pn = p ^ 1;
                #pragma unroll
                for (int r = 0; r < 8; ++r) {
                    st_cluster_f32(&xh[pn][je],       (uint32_t)r, c_new);
                    st_cluster_f32(&xh[pn][128 + je], (uint32_t)r, h_new);
                }
                const uint32_t nb = (pn == 0) ? bar0 : bar1;
                #pragma unroll
                for (int r = 0; r < 8; ++r) arrive_cluster(nb, (uint32_t)r);
            }
        }
    }
    cluster_sync_all();   // exit safety (peers may still target our smem)
}

// ============================================================================
// K1b: prepack B fragments (cs -> bf16 hi/lo, mma.sync col-major layout).
//      entry idx = nc*256 + kc*32 + lane; value uint4{hi01, hi23, lo01, lo23}
//      b0/b1 = cs[n][kc*16 + 2q], +1;  b2/b3 = cs[n][kc*16 + 2q + 8], +9;
//      n = nc*8 + lane/4, q = lane%4.
// ============================================================================
__global__ void k1b_prepack() {
    const float2* c2 = (const float2*)g_cs;     // [step][64 pairs]
    int tid = threadIdx.x;
    #pragma unroll
    for (int it = 0; it < 8; ++it) {
        int idx  = tid + it * 256;
        int lane = idx & 31;
        int kc   = (idx >> 5) & 7;
        int nc   = idx >> 8;
        int n    = nc * 8 + (lane >> 2);
        int q    = lane & 3;
        float2 p01 = c2[n * 64 + kc * 8 + q];
        float2 p23 = c2[n * 64 + kc * 8 + q + 4];
        uint32_t h01, l01, h23, l23;
        split2(p01, h01, l01);
        split2(p23, h23, l23);
        g_bfrag[idx] = make_uint4(h01, h23, l01, l23);
    }
}

// ============================================================================
// K2: scores + argmax via mma.sync bf16 3-segment (hi.hi + hi.lo + lo.hi).
//     grid = ceil(V/128) x 256. Warp w owns rows w*16..w*16+15, all 64 steps.
//     A fragments built in registers from coalesced global loads; no smem in
//     the hot path. 3 independent accumulator chains for HMMA ILP.
// ============================================================================
__global__ void __launch_bounds__(256, 1)
k2_score(const float* __restrict__ embed, float* __restrict__ out, int out_size) {
    __shared__ unsigned long long wb[8][STEPS];
    __shared__ int is_last;

    const int tid  = threadIdx.x;
    const int lane = tid & 31;
    const int w    = tid >> 5;
    const int q    = lane & 3;          // col-quad within fragment
    const int r4   = lane >> 2;         // fragment row 0..7
    const int tile = blockIdx.x;

    const int  row0 = tile * 128 + w * 16 + r4;     // this thread's two rows
    const int  row1 = row0 + 8;
    const bool v0 = row0 < VOCAB, v1 = row1 < VOCAB;

    // ---- A fragments from global + hi/lo split + row ssq ----
    uint32_t aH[8][4], aL[8][4];
    float ssq0 = 0.f, ssq1 = 0.f;
    {
        const float2* e2 = (const float2*)embed;
        const float2 z2 = make_float2(0.f, 0.f);
        size_t b0 = (size_t)(v0 ? row0 : 0) * 64;
        size_t b1 = (size_t)(v1 ? row1 : 0) * 64;
        #pragma unroll
        for (int kc = 0; kc < 8; ++kc) {
            float2 f00 = v0 ? e2[b0 + kc * 8 + q]     : z2;  // row0 cols 2q,2q+1
            float2 f01 = v0 ? e2[b0 + kc * 8 + q + 4] : z2;  // row0 cols +8,+9
            float2 f10 = v1 ? e2[b1 + kc * 8 + q]     : z2;  // row1
            float2 f11 = v1 ? e2[b1 + kc * 8 + q + 4] : z2;
            ssq0 = fmaf(f00.x, f00.x, fmaf(f00.y, f00.y,
                    fmaf(f01.x, f01.x, fmaf(f01.y, f01.y, ssq0))));
            ssq1 = fmaf(f10.x, f10.x, fmaf(f10.y, f10.y,
                    fmaf(f11.x, f11.x, fmaf(f11.y, f11.y, ssq1))));
            split2(f00, aH[kc][0], aL[kc][0]);   // {a0,a1}
            split2(f10, aH[kc][1], aL[kc][1]);   // {a2,a3}
            split2(f01, aH[kc][2], aL[kc][2]);   // {a4,a5}
            split2(f11, aH[kc][3], aL[kc][3]);   // {a6,a7}
        }
    }
    // quad-reduce ssq (lanes 4r..4r+3 share rows)
    ssq0 += __shfl_xor_sync(0xffffffffu, ssq0, 1);
    ssq0 += __shfl_xor_sync(0xffffffffu, ssq0, 2);
    ssq1 += __shfl_xor_sync(0xffffffffu, ssq1, 1);
    ssq1 += __shfl_xor_sync(0xffffffffu, ssq1, 2);
    const float iv0 = 1.0f / fmaxf(sqrtf(ssq0), 1e-8f);
    const float iv1 = 1.0f / fmaxf(sqrtf(ssq1), 1e-8f);

    // ---- main MMA: 3 independent chains ----
    float accA[8][4], accB[8][4], accC[8][4];
    #pragma unroll
    for (int nc = 0; nc < 8; ++nc)
        #pragma unroll
        for (int i = 0; i < 4; ++i) { accA[nc][i] = 0.f; accB[nc][i] = 0.f; accC[nc][i] = 0.f; }

    #pragma unroll
    for (int nc = 0; nc < 8; ++nc) {
        #pragma unroll
        for (int kc = 0; kc < 8; ++kc) {
            uint4 bb = g_bfrag[(nc * 8 + kc) * 32 + lane];
            mma16816(accA[nc], aH[kc], bb.x, bb.y);   // hi*hi
            mma16816(accB[nc], aH[kc], bb.z, bb.w);   // hi*lo
            mma16816(accC[nc], aL[kc], bb.x, bb.y);   // lo*hi
        }
    }

    // ---- per-step argmax ----
    // thread's scores: rows {row0,row1}, steps s = nc*8 + 2q + e (e=0,1)
    #pragma unroll
    for (int nc = 0; nc < 8; ++nc) {
        #pragma unroll
        for (int e = 0; e < 2; ++e) {
            float s0 = v0 ? (accA[nc][e]     + accB[nc][e]     + accC[nc][e])     * iv0 : -FLT_MAX;
            float s1 = v1 ? (accA[nc][2 + e] + accB[nc][2 + e] + accC[nc][2 + e]) * iv1 : -FLT_MAX;
            unsigned long long k0 =
                ((unsigned long long)enc_f32(s0) << 32) | (uint32_t)(~(uint32_t)row0);
            unsigned long long k1 =
                ((unsigned long long)enc_f32(s1) << 32) | (uint32_t)(~(uint32_t)row1);
            unsigned long long key = (k1 > k0) ? k1 : k0;
            #pragma unroll
            for (int off = 4; off < 32; off <<= 1) {
                unsigned long long o = __shfl_xor_sync(0xffffffffu, key, off);
                if (o > key) key = o;
            }
            if (r4 == 0) wb[w][nc * 8 + 2 * q + e] = key;   // lanes 0..3
        }
    }
    __syncthreads();
    if (tid < STEPS) {
        unsigned long long best = wb[0][tid];
        #pragma unroll
        for (int ww = 1; ww < 8; ++ww)
            if (wb[ww][tid] > best) best = wb[ww][tid];
        atomicMax(&g_best[tid], best);
    }

    // ---- last CTA decodes token ids ----
    __threadfence();
    __syncthreads();
    if (tid == 0) {
        int c = atomicAdd(&g_done, 1);
        is_last = (c == (int)gridDim.x - 1);
    }
    __syncthreads();
    if (is_last) {
        if (tid == 0) g_done = 0;
        __threadfence();
        if (tid < STEPS) {
            uint32_t idx = ~((uint32_t)(g_best[tid] & 0xffffffffu));
            out[(out_size - STEPS) + tid] = (float)idx;
        }
    }
}

// ============================================================================
extern "C" void kernel_launch(void* const* d_in, const int* in_sizes, int n_in,
                              void* d_out, int out_size) {
    const float* inp   = (const float*)d_in[0];
    const float* embed = (const float*)d_in[1];
    const float* w_ih  = (const float*)d_in[2];
    const float* w_hh  = (const float*)d_in[3];
    const float* b_ih  = (const float*)d_in[4];
    const float* b_hh  = (const float*)d_in[5];
    float* out = (float*)d_out;
    (void)in_sizes; (void)n_in;

    const int write_cs = (out_size >= STEPS * 128 + STEPS) ? 1 : 0;

    // Phase A: cluster-of-8 LSTM
    {
        cudaLaunchConfig_t cfg = {};
        cfg.gridDim  = dim3(8, 1, 1);
        cfg.blockDim = dim3(256, 1, 1);
        cfg.dynamicSmemBytes = 0;
        cfg.stream = 0;
        cudaLaunchAttribute attrs[1];
        attrs[0].id = cudaLaunchAttributeClusterDimension;
        attrs[0].val.clusterDim.x = 8;
        attrs[0].val.clusterDim.y = 1;
        attrs[0].val.clusterDim.z = 1;
        cfg.attrs = attrs;
        cfg.numAttrs = 1;
        cudaLaunchKernelEx(&cfg, k1_lstm, embed, w_ih, w_hh, inp, b_ih, b_hh,
                           out, write_cs);
    }

    // Phase A.5: prepack B fragments
    k1b_prepack<<<1, 256>>>();

    // Phase B: mma.sync scoring + argmax + decode
    const int ntiles = (VOCAB + 127) / 128;
    k2_score<<<ntiles, 256>>>(embed, out, out_size);
}

// round 5
// speedup vs baseline: 1.2297x; 1.2297x over previous
#include <cuda_runtime.h>
#include <cuda_bf16.h>
#include <cstdint>
#include <cfloat>

#define VOCAB   500000
#define EMB_D   128
#define HID     128
#define STEPS   64

// ---------------- device globals (scratch; no allocation allowed) ----------
__device__ float               g_cs[STEPS * HID];    // cell states [step][k]
__device__ uint4               g_bfrag[2048];        // prepacked B frags [nc][kc][lane]
__device__ unsigned long long  g_best[STEPS];        // (enc(score)<<32)|~idx
__device__ int                 g_done = 0;           // last-CTA counter (self-reset)

// ---------------- helpers ---------------------------------------------------
__device__ __forceinline__ uint32_t enc_f32(float f) {
    uint32_t u = __float_as_uint(f);
    return (u & 0x80000000u) ? ~u : (u | 0x80000000u);
}
__device__ __forceinline__ uint32_t smem_u32(const void* p) {
    return (uint32_t)__cvta_generic_to_shared(p);
}
__device__ __forceinline__ uint32_t mapa_rank(uint32_t local, uint32_t rank) {
    uint32_t r;
    asm volatile("mapa.shared::cluster.u32 %0, %1, %2;" : "=r"(r) : "r"(local), "r"(rank));
    return r;
}
#define WAIT_PARITY_CLUSTER(mbar, par) do {                                    \
    uint32_t _d;                                                               \
    do {                                                                       \
        asm volatile("{\n\t.reg .pred p;\n\t"                                  \
            "mbarrier.try_wait.parity.acquire.cluster.shared::cta.b64 p, [%1], %2, 0x989680;\n\t" \
            "selp.b32 %0, 1, 0, p;\n\t}"                                       \
            : "=r"(_d) : "r"(mbar), "r"(par) : "memory");                      \
    } while (!_d); } while (0)
#define MBAR_INIT(mbar, cnt) \
    asm volatile("mbarrier.init.shared.b64 [%0], %1;" :: "r"(mbar), "r"(cnt) : "memory")

__device__ __forceinline__ uint32_t my_cluster_rank() {
    uint32_t r; asm("mov.u32 %0, %%cluster_ctarank;" : "=r"(r)); return r;
}
__device__ __forceinline__ void cluster_sync_all() {
    asm volatile("barrier.cluster.arrive.aligned;" ::: "memory");
    asm volatile("barrier.cluster.wait.aligned;"   ::: "memory");
}
__device__ __forceinline__ float sigf(float x) { return 1.0f / (1.0f + expf(-x)); }

// split a float2 into bf16x2 hi and bf16x2 lo(residual)
__device__ __forceinline__ void split2(float2 v, uint32_t& hi, uint32_t& lo) {
    __nv_bfloat162 h = __floats2bfloat162_rn(v.x, v.y);
    hi = *(uint32_t*)&h;
    float rx = v.x - __bfloat162float(h.x);
    float ry = v.y - __bfloat162float(h.y);
    __nv_bfloat162 l = __floats2bfloat162_rn(rx, ry);
    lo = *(uint32_t*)&l;
}

// m16n8k16 row.col f32.bf16.bf16.f32
__device__ __forceinline__ void mma16816(float* c, const uint32_t* a,
                                         uint32_t b0, uint32_t b1) {
    asm volatile(
        "mma.sync.aligned.m16n8k16.row.col.f32.bf16.bf16.f32 "
        "{%0,%1,%2,%3}, {%4,%5,%6,%7}, {%8,%9}, {%0,%1,%2,%3};"
        : "+f"(c[0]), "+f"(c[1]), "+f"(c[2]), "+f"(c[3])
        : "r"(a[0]), "r"(a[1]), "r"(a[2]), "r"(a[3]), "r"(b0), "r"(b1));
}

// ============================================================================
// K1: 64 LSTM steps (cluster of 8 CTAs x 256 threads).
//     Aggregated state exchange: epilogue stages 32 floats locally, then 8
//     sender threads each do 16 remote b64 stores + ONE release-arrive
//     (8 arrivals per barrier instead of 128 release-fenced ones).
// ============================================================================
__global__ void __launch_bounds__(256, 1)
k1_lstm(const float* __restrict__ embed,
        const float* __restrict__ w_ih,
        const float* __restrict__ w_hh,
        const float* __restrict__ inp,
        const float* __restrict__ b_ih,
        const float* __restrict__ b_hh,
        float* __restrict__ out, int write_cs) {
    __shared__ float xh[2][256];
    __shared__ float gates_sm[64];
    __shared__ float Ksm[64];
    __shared__ float inp_sm[128];
    __shared__ alignas(8) float stage[32];          // [c x16 | h x16]
    __shared__ alignas(8) unsigned long long barr[2];

    const int tid  = threadIdx.x;
    const uint32_t rank = my_cluster_rank();
    const uint32_t bar0 = smem_u32(&barr[0]);
    const uint32_t bar1 = smem_u32(&barr[1]);

    const int lr   = tid >> 2;          // local gate row 0..63
    const int part = tid & 3;           // column quarter
    const int g    = lr >> 4;           // gate 0..3
    const int jj   = lr & 15;           // local hidden idx
    const int j    = (int)rank * 16 + jj;
    const int grow = g * 128 + j;       // global gate row

    if (rank == 0 && tid < STEPS) g_best[tid] = 0ull;

    if (tid == 0) { MBAR_INIT(bar0, 8); MBAR_INIT(bar1, 8); }
    if (tid < 128) {
        inp_sm[tid]      = inp[tid];
        xh[0][tid]       = embed[tid];
        xh[0][128 + tid] = 0.f;
    }

    float w[64];
    #pragma unroll
    for (int cc = 0; cc < 64; ++cc) {
        int col = part * 64 + cc;
        w[cc] = (col < 128) ? w_ih[grow * 256 + col]
                            : w_hh[grow * 128 + (col - 128)];
    }
    __syncthreads();
    cluster_sync_all();   // all barriers initialized before any arrive

    // fold K[grow] = b_ih + b_hh + W_ih[:,128:] @ inp
    {
        const float* wr = w_ih + grow * 256 + 128 + part * 32;
        float s = 0.f;
        #pragma unroll 8
        for (int c = 0; c < 32; ++c) s = fmaf(wr[c], inp_sm[part * 32 + c], s);
        s += __shfl_xor_sync(0xffffffffu, s, 1);
        s += __shfl_xor_sync(0xffffffffu, s, 2);
        if (part == 0) Ksm[lr] = s + b_ih[grow] + b_hh[grow];
    }
    __syncthreads();

    float c_reg = 0.f, k0v = 0.f, k1v = 0.f, k2v = 0.f, k3v = 0.f;
    if (tid < 16) {
        k0v = Ksm[ 0 + tid]; k1v = Ksm[16 + tid];
        k2v = Ksm[32 + tid]; k3v = Ksm[48 + tid];
    }
    __syncthreads();

    int cnt0 = 0, cnt1 = 0;
    for (int step = 0; step < STEPS; ++step) {
        if (step > 0) {
            if (step & 1) { WAIT_PARITY_CLUSTER(bar1, cnt1 & 1); ++cnt1; }
            else          { WAIT_PARITY_CLUSTER(bar0, cnt0 & 1); ++cnt0; }
        }
        const int p = step & 1;
        const float4* xv = (const float4*)&xh[p][part * 64];
        float a0 = 0.f, a1 = 0.f, a2 = 0.f, a3 = 0.f;
        #pragma unroll
        for (int q = 0; q < 16; ++q) {
            float4 v = xv[q];
            a0 = fmaf(w[4*q + 0], v.x, a0);
            a1 = fmaf(w[4*q + 1], v.y, a1);
            a2 = fmaf(w[4*q + 2], v.z, a2);
            a3 = fmaf(w[4*q + 3], v.w, a3);
        }
        float acc = (a0 + a1) + (a2 + a3);
        acc += __shfl_xor_sync(0xffffffffu, acc, 1);
        acc += __shfl_xor_sync(0xffffffffu, acc, 2);
        if (part == 0) gates_sm[lr] = acc;
        __syncthreads();

        if (tid < 16) {
            int je = (int)rank * 16 + tid;
            float gi = gates_sm[ 0 + tid] + k0v;
            float gf = gates_sm[16 + tid] + k1v;
            float gg = gates_sm[32 + tid] + k2v;
            float go = gates_sm[48 + tid] + k3v;
            float iv = sigf(gi), fv = sigf(gf), gv = tanhf(gg), ov = sigf(go);
            float c_new = fv * c_reg + iv * gv;
            float h_new = ov * tanhf(c_new);
            c_reg = c_new;
            if (write_cs) out[step * 128 + je] = c_new;
            g_cs[step * 128 + je] = c_new;
            stage[tid]      = c_new;
            stage[16 + tid] = h_new;
        }
        __syncthreads();

        if (step < STEPS - 1 && tid < 8) {
            const int pn = p ^ 1;
            const unsigned long long* sc = (const unsigned long long*)&stage[0];
            const unsigned long long* sh = (const unsigned long long*)&stage[16];
            uint32_t ac = smem_u32(&xh[pn][(int)rank * 16]);
            uint32_t ah = smem_u32(&xh[pn][128 + (int)rank * 16]);
            uint32_t rc = mapa_rank(ac, (uint32_t)tid);
            uint32_t rh = mapa_rank(ah, (uint32_t)tid);
            uint32_t rb = mapa_rank((pn == 0) ? bar0 : bar1, (uint32_t)tid);
            #pragma unroll
            for (int i = 0; i < 8; ++i) {
                asm volatile("st.shared::cluster.b64 [%0], %1;"
                             :: "r"(rc + 8 * i), "l"(sc[i]) : "memory");
                asm volatile("st.shared::cluster.b64 [%0], %1;"
                             :: "r"(rh + 8 * i), "l"(sh[i]) : "memory");
            }
            asm volatile("mbarrier.arrive.release.cluster.shared::cluster.b64 _, [%0];"
                         :: "r"(rb) : "memory");
        }
    }
    cluster_sync_all();   // exit safety
}

// ============================================================================
// K1b: prepack B fragments (cs -> bf16 hi/lo, mma.sync col-major layout).
// ============================================================================
__global__ void k1b_prepack() {
    const float2* c2 = (const float2*)g_cs;     // [step][64 pairs]
    int tid = threadIdx.x;
    #pragma unroll
    for (int it = 0; it < 8; ++it) {
        int idx  = tid + it * 256;
        int lane = idx & 31;
        int kc   = (idx >> 5) & 7;
        int nc   = idx >> 8;
        int n    = nc * 8 + (lane >> 2);
        int q    = lane & 3;
        float2 p01 = c2[n * 64 + kc * 8 + q];
        float2 p23 = c2[n * 64 + kc * 8 + q + 4];
        uint32_t h01, l01, h23, l23;
        split2(p01, h01, l01);
        split2(p23, h23, l23);
        g_bfrag[idx] = make_uint4(h01, h23, l01, l23);
    }
}

// ============================================================================
// K2: scores + argmax via mma.sync bf16 3-segment (hi.hi + hi.lo + lo.hi).
//     Per-nc accumulators (12 live regs) to avoid the R4 spill blowup.
// ============================================================================
__global__ void __launch_bounds__(256, 1)
k2_score(const float* __restrict__ embed, float* __restrict__ out, int out_size) {
    __shared__ unsigned long long wb[8][STEPS];
    __shared__ int is_last;

    const int tid  = threadIdx.x;
    const int lane = tid & 31;
    const int w    = tid >> 5;
    const int q    = lane & 3;          // col-quad within fragment
    const int r4   = lane >> 2;         // fragment row 0..7
    const int tile = blockIdx.x;

    const int  row0 = tile * 128 + w * 16 + r4;
    const int  row1 = row0 + 8;
    const bool v0 = row0 < VOCAB, v1 = row1 < VOCAB;

    // ---- A fragments from global + hi/lo split + row ssq ----
    uint32_t aH[8][4], aL[8][4];
    float ssq0 = 0.f, ssq1 = 0.f;
    {
        const float2* e2 = (const float2*)embed;
        const float2 z2 = make_float2(0.f, 0.f);
        size_t b0 = (size_t)(v0 ? row0 : 0) * 64;
        size_t b1 = (size_t)(v1 ? row1 : 0) * 64;
        #pragma unroll
        for (int kc = 0; kc < 8; ++kc) {
            float2 f00 = v0 ? e2[b0 + kc * 8 + q]     : z2;
            float2 f01 = v0 ? e2[b0 + kc * 8 + q + 4] : z2;
            float2 f10 = v1 ? e2[b1 + kc * 8 + q]     : z2;
            float2 f11 = v1 ? e2[b1 + kc * 8 + q + 4] : z2;
            ssq0 = fmaf(f00.x, f00.x, fmaf(f00.y, f00.y,
                    fmaf(f01.x, f01.x, fmaf(f01.y, f01.y, ssq0))));
            ssq1 = fmaf(f10.x, f10.x, fmaf(f10.y, f10.y,
                    fmaf(f11.x, f11.x, fmaf(f11.y, f11.y, ssq1))));
            split2(f00, aH[kc][0], aL[kc][0]);
            split2(f10, aH[kc][1], aL[kc][1]);
            split2(f01, aH[kc][2], aL[kc][2]);
            split2(f11, aH[kc][3], aL[kc][3]);
        }
    }
    ssq0 += __shfl_xor_sync(0xffffffffu, ssq0, 1);
    ssq0 += __shfl_xor_sync(0xffffffffu, ssq0, 2);
    ssq1 += __shfl_xor_sync(0xffffffffu, ssq1, 1);
    ssq1 += __shfl_xor_sync(0xffffffffu, ssq1, 2);
    const float iv0 = 1.0f / fmaxf(sqrtf(ssq0), 1e-8f);
    const float iv1 = 1.0f / fmaxf(sqrtf(ssq1), 1e-8f);

    // ---- main MMA + per-nc argmax (only 12 acc regs live at a time) ----
    #pragma unroll
    for (int nc = 0; nc < 8; ++nc) {
        float a1[4] = {0.f, 0.f, 0.f, 0.f};
        float a2[4] = {0.f, 0.f, 0.f, 0.f};
        float a3[4] = {0.f, 0.f, 0.f, 0.f};
        #pragma unroll
        for (int kc = 0; kc < 8; ++kc) {
            uint4 bb = g_bfrag[(nc * 8 + kc) * 32 + lane];
            mma16816(a1, aH[kc], bb.x, bb.y);   // hi*hi
            mma16816(a2, aH[kc], bb.z, bb.w);   // hi*lo
            mma16816(a3, aL[kc], bb.x, bb.y);   // lo*hi
        }
        #pragma unroll
        for (int e = 0; e < 2; ++e) {
            float s0 = v0 ? (a1[e]     + a2[e]     + a3[e])     * iv0 : -FLT_MAX;
            float s1 = v1 ? (a1[2 + e] + a2[2 + e] + a3[2 + e]) * iv1 : -FLT_MAX;
            unsigned long long k0 =
                ((unsigned long long)enc_f32(s0) << 32) | (uint32_t)(~(uint32_t)row0);
            unsigned long long k1 =
                ((unsigned long long)enc_f32(s1) << 32) | (uint32_t)(~(uint32_t)row1);
            unsigned long long key = (k1 > k0) ? k1 : k0;
            #pragma unroll
            for (int off = 4; off < 32; off <<= 1) {
                unsigned long long o = __shfl_xor_sync(0xffffffffu, key, off);
                if (o > key) key = o;
            }
            if (r4 == 0) wb[w][nc * 8 + 2 * q + e] = key;   // lanes 0..3
        }
    }
    __syncthreads();
    if (tid < STEPS) {
        unsigned long long best = wb[0][tid];
        #pragma unroll
        for (int ww = 1; ww < 8; ++ww)
            if (wb[ww][tid] > best) best = wb[ww][tid];
        // snapshot-gated atomic (g_best only grows -> skipping when covered is safe)
        unsigned long long cur = *(volatile unsigned long long*)&g_best[tid];
        if (best > cur) atomicMax(&g_best[tid], best);
    }

    // ---- last CTA decodes token ids ----
    __threadfence();
    __syncthreads();
    if (tid == 0) {
        int c = atomicAdd(&g_done, 1);
        is_last = (c == (int)gridDim.x - 1);
    }
    __syncthreads();
    if (is_last) {
        if (tid == 0) g_done = 0;
        __threadfence();
        if (tid < STEPS) {
            uint32_t idx = ~((uint32_t)(g_best[tid] & 0xffffffffu));
            out[(out_size - STEPS) + tid] = (float)idx;
        }
    }
}

// ============================================================================
extern "C" void kernel_launch(void* const* d_in, const int* in_sizes, int n_in,
                              void* d_out, int out_size) {
    const float* inp   = (const float*)d_in[0];
    const float* embed = (const float*)d_in[1];
    const float* w_ih  = (const float*)d_in[2];
    const float* w_hh  = (const float*)d_in[3];
    const float* b_ih  = (const float*)d_in[4];
    const float* b_hh  = (const float*)d_in[5];
    float* out = (float*)d_out;
    (void)in_sizes; (void)n_in;

    const int write_cs = (out_size >= STEPS * 128 + STEPS) ? 1 : 0;

    // Phase A: cluster-of-8 LSTM
    {
        cudaLaunchConfig_t cfg = {};
        cfg.gridDim  = dim3(8, 1, 1);
        cfg.blockDim = dim3(256, 1, 1);
        cfg.dynamicSmemBytes = 0;
        cfg.stream = 0;
        cudaLaunchAttribute attrs[1];
        attrs[0].id = cudaLaunchAttributeClusterDimension;
        attrs[0].val.clusterDim.x = 8;
        attrs[0].val.clusterDim.y = 1;
        attrs[0].val.clusterDim.z = 1;
        cfg.attrs = attrs;
        cfg.numAttrs = 1;
        cudaLaunchKernelEx(&cfg, k1_lstm, embed, w_ih, w_hh, inp, b_ih, b_hh,
                           out, write_cs);
    }

    // Phase A.5: prepack B fragments
    k1b_prepack<<<1, 256>>>();

    // Phase B: mma.sync scoring + argmax + decode
    const int ntiles = (VOCAB + 127) / 128;
    k2_score<<<ntiles, 256>>>(embed, out, out_size);
}

// round 7
// speedup vs baseline: 1.4149x; 1.1506x over previous
#include <cuda_runtime.h>
#include <cuda_bf16.h>
#include <cstdint>
#include <cfloat>

#define VOCAB   500000
#define EMB_D   128
#define HID     128
#define STEPS   64
#define NTILES  3907          // ceil(VOCAB/128)
#define K2CTAS  148

// ---------------- device globals (scratch; no allocation allowed) ----------
__device__ float               g_cs[STEPS * HID];    // cell states [step][k]
__device__ unsigned long long  g_best[STEPS];        // (enc(score)<<32)|~idx
__device__ int                 g_done = 0;           // last-CTA counter (self-reset)

// ---------------- helpers ---------------------------------------------------
__device__ __forceinline__ uint32_t enc_f32(float f) {
    uint32_t u = __float_as_uint(f);
    return (u & 0x80000000u) ? ~u : (u | 0x80000000u);
}
__device__ __forceinline__ uint32_t smem_u32(const void* p) {
    return (uint32_t)__cvta_generic_to_shared(p);
}
__device__ __forceinline__ uint32_t mapa_rank(uint32_t local, uint32_t rank) {
    uint32_t r;
    asm volatile("mapa.shared::cluster.u32 %0, %1, %2;" : "=r"(r) : "r"(local), "r"(rank));
    return r;
}
#define WAIT_PARITY_CLUSTER(mbar, par) do {                                    \
    uint32_t _d;                                                               \
    do {                                                                       \
        asm volatile("{\n\t.reg .pred p;\n\t"                                  \
            "mbarrier.try_wait.parity.acquire.cluster.shared::cta.b64 p, [%1], %2, 0x989680;\n\t" \
            "selp.b32 %0, 1, 0, p;\n\t}"                                       \
            : "=r"(_d) : "r"(mbar), "r"(par) : "memory");                      \
    } while (!_d); } while (0)
#define MBAR_INIT(mbar, cnt) \
    asm volatile("mbarrier.init.shared.b64 [%0], %1;" :: "r"(mbar), "r"(cnt) : "memory")

__device__ __forceinline__ uint32_t my_cluster_rank() {
    uint32_t r; asm("mov.u32 %0, %%cluster_ctarank;" : "=r"(r)); return r;
}
__device__ __forceinline__ void cluster_sync_all() {
    asm volatile("barrier.cluster.arrive.aligned;" ::: "memory");
    asm volatile("barrier.cluster.wait.aligned;"   ::: "memory");
}
// fast activations (MUFU-based, ~1e-6 rel err; overflow-safe)
__device__ __forceinline__ float sig_fast(float x) {
    return __fdividef(1.0f, 1.0f + __expf(-x));
}
__device__ __forceinline__ float tanh_fast(float x) {
    return 1.0f - __fdividef(2.0f, __expf(2.0f * x) + 1.0f);
}

// split a float2 into bf16x2 hi and bf16x2 lo(residual)
__device__ __forceinline__ void split2(float2 v, uint32_t& hi, uint32_t& lo) {
    __nv_bfloat162 h = __floats2bfloat162_rn(v.x, v.y);
    hi = *(uint32_t*)&h;
    float rx = v.x - __bfloat162float(h.x);
    float ry = v.y - __bfloat162float(h.y);
    __nv_bfloat162 l = __floats2bfloat162_rn(rx, ry);
    lo = *(uint32_t*)&l;
}

// m16n8k16 row.col f32.bf16.bf16.f32
__device__ __forceinline__ void mma16816(float* c, const uint32_t* a,
                                         uint32_t b0, uint32_t b1) {
    asm volatile(
        "mma.sync.aligned.m16n8k16.row.col.f32.bf16.bf16.f32 "
        "{%0,%1,%2,%3}, {%4,%5,%6,%7}, {%8,%9}, {%0,%1,%2,%3};"
        : "+f"(c[0]), "+f"(c[1]), "+f"(c[2]), "+f"(c[3])
        : "r"(a[0]), "r"(a[1]), "r"(a[2]), "r"(a[3]), "r"(b0), "r"(b1));
}

// ============================================================================
// K1: 64 LSTM steps (cluster of 8 CTAs x 256 threads).
//     One __syncthreads per step; MUFU activations; hoisted mapa; aggregated
//     DSMEM state exchange (8 senders x 16 b64 stores + 1 release-arrive).
// ============================================================================
__global__ void __launch_bounds__(256, 1)
k1_lstm(const float* __restrict__ embed,
        const float* __restrict__ w_ih,
        const float* __restrict__ w_hh,
        const float* __restrict__ inp,
        const float* __restrict__ b_ih,
        const float* __restrict__ b_hh,
        float* __restrict__ out, int write_cs) {
    __shared__ float xh[2][256];
    __shared__ float gates_sm[64];
    __shared__ float Ksm[64];
    __shared__ float inp_sm[128];
    __shared__ alignas(8) float stage[32];          // [c x16 | h x16]
    __shared__ alignas(8) unsigned long long barr[2];

    const int tid  = threadIdx.x;
    const uint32_t rank = my_cluster_rank();
    const uint32_t bar0 = smem_u32(&barr[0]);
    const uint32_t bar1 = smem_u32(&barr[1]);

    const int lr   = tid >> 2;          // local gate row 0..63
    const int part = tid & 3;           // column quarter
    const int g    = lr >> 4;           // gate 0..3
    const int jj   = lr & 15;           // local hidden idx
    const int j    = (int)rank * 16 + jj;
    const int grow = g * 128 + j;       // global gate row

    if (rank == 0 && tid < STEPS) g_best[tid] = 0ull;

    if (tid == 0) { MBAR_INIT(bar0, 8); MBAR_INIT(bar1, 8); }
    if (tid < 128) {
        inp_sm[tid]      = inp[tid];
        xh[0][tid]       = embed[tid];
        xh[0][128 + tid] = 0.f;
    }

    float w[64];
    #pragma unroll
    for (int cc = 0; cc < 64; ++cc) {
        int col = part * 64 + cc;
        w[cc] = (col < 128) ? w_ih[grow * 256 + col]
                            : w_hh[grow * 128 + (col - 128)];
    }

    // hoisted remote addresses for senders (tid<8 -> destination rank = tid)
    uint32_t rcA[2], rhA[2], rbA[2];
    if (tid < 8) {
        #pragma unroll
        for (int pn = 0; pn < 2; ++pn) {
            rcA[pn] = mapa_rank(smem_u32(&xh[pn][(int)rank * 16]),       (uint32_t)tid);
            rhA[pn] = mapa_rank(smem_u32(&xh[pn][128 + (int)rank * 16]), (uint32_t)tid);
            rbA[pn] = mapa_rank((pn == 0) ? bar0 : bar1,                 (uint32_t)tid);
        }
    }
    __syncthreads();
    cluster_sync_all();   // all barriers initialized before any arrive

    // fold K[grow] = b_ih + b_hh + W_ih[:,128:] @ inp
    {
        const float* wr = w_ih + grow * 256 + 128 + part * 32;
        float s = 0.f;
        #pragma unroll 8
        for (int c = 0; c < 32; ++c) s = fmaf(wr[c], inp_sm[part * 32 + c], s);
        s += __shfl_xor_sync(0xffffffffu, s, 1);
        s += __shfl_xor_sync(0xffffffffu, s, 2);
        if (part == 0) Ksm[lr] = s + b_ih[grow] + b_hh[grow];
    }
    __syncthreads();

    float c_reg = 0.f, k0v = 0.f, k1v = 0.f, k2v = 0.f, k3v = 0.f;
    if (tid < 16) {
        k0v = Ksm[ 0 + tid]; k1v = Ksm[16 + tid];
        k2v = Ksm[32 + tid]; k3v = Ksm[48 + tid];
    }
    __syncthreads();

    int cnt0 = 0, cnt1 = 0;
    for (int step = 0; step < STEPS; ++step) {
        if (step > 0) {
            if (step & 1) { WAIT_PARITY_CLUSTER(bar1, cnt1 & 1); ++cnt1; }
            else          { WAIT_PARITY_CLUSTER(bar0, cnt0 & 1); ++cnt0; }
        }
        const int p = step & 1;
        const float4* xv = (const float4*)&xh[p][part * 64];
        float a0 = 0.f, a1 = 0.f, a2 = 0.f, a3 = 0.f;
        #pragma unroll
        for (int qq = 0; qq < 16; ++qq) {
            float4 v = xv[qq];
            a0 = fmaf(w[4*qq + 0], v.x, a0);
            a1 = fmaf(w[4*qq + 1], v.y, a1);
            a2 = fmaf(w[4*qq + 2], v.z, a2);
            a3 = fmaf(w[4*qq + 3], v.w, a3);
        }
        float acc = (a0 + a1) + (a2 + a3);
        acc += __shfl_xor_sync(0xffffffffu, acc, 1);
        acc += __shfl_xor_sync(0xffffffffu, acc, 2);
        if (part == 0) gates_sm[lr] = acc;
        __syncthreads();          // the ONLY block barrier per step

        if (tid < 32) {           // whole warp 0 (epilogue + senders)
            if (tid < 16) {
                int je = (int)rank * 16 + tid;
                float gi = gates_sm[ 0 + tid] + k0v;
                float gf = gates_sm[16 + tid] + k1v;
                float gg = gates_sm[32 + tid] + k2v;
                float go = gates_sm[48 + tid] + k3v;
                float iv = sig_fast(gi), fv = sig_fast(gf);
                float gv = tanh_fast(gg), ov = sig_fast(go);
                float c_new = fv * c_reg + iv * gv;
                float h_new = ov * tanh_fast(c_new);
                c_reg = c_new;
                if (write_cs) out[step * 128 + je] = c_new;
                g_cs[step * 128 + je] = c_new;
                stage[tid]      = c_new;
                stage[16 + tid] = h_new;
            }
            __syncwarp();
            if (step < STEPS - 1 && tid < 8) {
                const int pn = p ^ 1;
                const unsigned long long* sc = (const unsigned long long*)&stage[0];
                const unsigned long long* sh = (const unsigned long long*)&stage[16];
                uint32_t rc = rcA[pn], rh = rhA[pn], rb = rbA[pn];
                #pragma unroll
                for (int i = 0; i < 8; ++i) {
                    asm volatile("st.shared::cluster.b64 [%0], %1;"
                                 :: "r"(rc + 8 * i), "l"(sc[i]) : "memory");
                    asm volatile("st.shared::cluster.b64 [%0], %1;"
                                 :: "r"(rh + 8 * i), "l"(sh[i]) : "memory");
                }
                asm volatile("mbarrier.arrive.release.cluster.shared::cluster.b64 _, [%0];"
                             :: "r"(rb) : "memory");
            }
        }
    }
    cluster_sync_all();   // exit safety
}

// ============================================================================
// K2: persistent scorer. 148 CTAs x 256 threads; CTA b handles tiles
//     b, b+148, ... Each tile: 128 rows x 64 steps, bf16 3-segment mma.sync
//     (hi.hi + hi.lo + lo.hi == exact-enough fp32). B fragments built once
//     per CTA in smem; next tile's A prefetched into registers during MMA.
// ============================================================================
__global__ void __launch_bounds__(256, 1)
k2_score(const float* __restrict__ embed, float* __restrict__ out, int out_size) {
    __shared__ uint4 sbfrag[2048];                  // [nc*8+kc][lane], 32KB
    __shared__ unsigned long long wb[8][STEPS];
    __shared__ int is_last;

    const int tid  = threadIdx.x;
    const int lane = tid & 31;
    const int w    = tid >> 5;
    const int q    = lane & 3;          // col-quad within fragment
    const int r4   = lane >> 2;         // fragment row 0..7

    // ---- build B fragments from g_cs into smem (once per CTA) ----
    {
        const float2* c2 = (const float2*)g_cs;
        #pragma unroll
        for (int it = 0; it < 8; ++it) {
            int idx  = tid + it * 256;
            int ln   = idx & 31;
            int kc   = (idx >> 5) & 7;
            int nc   = idx >> 8;
            int n    = nc * 8 + (ln >> 2);
            int qq   = ln & 3;
            float2 p01 = c2[n * 64 + kc * 8 + qq];
            float2 p23 = c2[n * 64 + kc * 8 + qq + 4];
            uint32_t h01, l01, h23, l23;
            split2(p01, h01, l01);
            split2(p23, h23, l23);
            sbfrag[idx] = make_uint4(h01, h23, l01, l23);
        }
    }
    __syncthreads();

    const float2* e2 = (const float2*)embed;
    float2 F[32];                       // raw A prefetch buffer (64 regs)

#define PREFETCH_TILE(TT) do {                                                 \
    int _r0 = (TT) * 128 + w * 16 + r4;                                        \
    int _r1 = _r0 + 8;                                                         \
    size_t _b0 = (size_t)((_r0 < VOCAB) ? _r0 : 0) * 64;                       \
    size_t _b1 = (size_t)((_r1 < VOCAB) ? _r1 : 0) * 64;                       \
    _Pragma("unroll")                                                          \
    for (int kc = 0; kc < 8; ++kc) {                                           \
        F[kc * 4 + 0] = e2[_b0 + kc * 8 + q];                                  \
        F[kc * 4 + 1] = e2[_b1 + kc * 8 + q];                                  \
        F[kc * 4 + 2] = e2[_b0 + kc * 8 + q + 4];                              \
        F[kc * 4 + 3] = e2[_b1 + kc * 8 + q + 4];                              \
    } } while (0)

    int t = blockIdx.x;
    if (t < NTILES) PREFETCH_TILE(t);

    while (t < NTILES) {
        const int  row0 = t * 128 + w * 16 + r4;
        const int  row1 = row0 + 8;
        const bool v0 = row0 < VOCAB, v1 = row1 < VOCAB;

        // ---- split current A + row ssq ----
        uint32_t aH[8][4], aL[8][4];
        float ssq0 = 0.f, ssq1 = 0.f;
        const float2 z2 = make_float2(0.f, 0.f);
        #pragma unroll
        for (int kc = 0; kc < 8; ++kc) {
            float2 f00 = v0 ? F[kc * 4 + 0] : z2;
            float2 f10 = v1 ? F[kc * 4 + 1] : z2;
            float2 f01 = v0 ? F[kc * 4 + 2] : z2;
            float2 f11 = v1 ? F[kc * 4 + 3] : z2;
            ssq0 = fmaf(f00.x, f00.x, fmaf(f00.y, f00.y,
                    fmaf(f01.x, f01.x, fmaf(f01.y, f01.y, ssq0))));
            ssq1 = fmaf(f10.x, f10.x, fmaf(f10.y, f10.y,
                    fmaf(f11.x, f11.x, fmaf(f11.y, f11.y, ssq1))));
            split2(f00, aH[kc][0], aL[kc][0]);
            split2(f10, aH[kc][1], aL[kc][1]);
            split2(f01, aH[kc][2], aL[kc][2]);
            split2(f11, aH[kc][3], aL[kc][3]);
        }
        ssq0 += __shfl_xor_sync(0xffffffffu, ssq0, 1);
        ssq0 += __shfl_xor_sync(0xffffffffu, ssq0, 2);
        ssq1 += __shfl_xor_sync(0xffffffffu, ssq1, 1);
        ssq1 += __shfl_xor_sync(0xffffffffu, ssq1, 2);
        const float iv0 = 1.0f / fmaxf(sqrtf(ssq0), 1e-8f);
        const float iv1 = 1.0f / fmaxf(sqrtf(ssq1), 1e-8f);

        // ---- prefetch next tile (LDGs overlap the MMA loop below) ----
        const int tn = t + K2CTAS;
        if (tn < NTILES) PREFETCH_TILE(tn);

        // ---- MMA + per-nc argmax ----
        #pragma unroll
        for (int nc = 0; nc < 8; ++nc) {
            float c1[4] = {0.f, 0.f, 0.f, 0.f};
            float c2a[4] = {0.f, 0.f, 0.f, 0.f};
            float c3[4] = {0.f, 0.f, 0.f, 0.f};
            #pragma unroll
            for (int kc = 0; kc < 8; ++kc) {
                uint4 bb = sbfrag[(nc * 8 + kc) * 32 + lane];
                mma16816(c1,  aH[kc], bb.x, bb.y);   // hi*hi
                mma16816(c2a, aH[kc], bb.z, bb.w);   // hi*lo
                mma16816(c3,  aL[kc], bb.x, bb.y);   // lo*hi
            }
            #pragma unroll
            for (int e = 0; e < 2; ++e) {
                float s0 = v0 ? (c1[e]     + c2a[e]     + c3[e])     * iv0 : -FLT_MAX;
                float s1 = v1 ? (c1[2 + e] + c2a[2 + e] + c3[2 + e]) * iv1 : -FLT_MAX;
                unsigned long long k0 =
                    ((unsigned long long)enc_f32(s0) << 32) | (uint32_t)(~(uint32_t)row0);
                unsigned long long k1 =
                    ((unsigned long long)enc_f32(s1) << 32) | (uint32_t)(~(uint32_t)row1);
                unsigned long long key = (k1 > k0) ? k1 : k0;
                #pragma unroll
                for (int off = 4; off < 32; off <<= 1) {
                    unsigned long long o = __shfl_xor_sync(0xffffffffu, key, off);
                    if (o > key) key = o;
                }
                if (r4 == 0) wb[w][nc * 8 + 2 * q + e] = key;
            }
        }
        __syncthreads();
        if (tid < STEPS) {
            unsigned long long best = wb[0][tid];
            #pragma unroll
            for (int ww = 1; ww < 8; ++ww)
                if (wb[ww][tid] > best) best = wb[ww][tid];
            unsigned long long cur = *(volatile unsigned long long*)&g_best[tid];
            if (best > cur) atomicMax(&g_best[tid], best);
        }
        __syncthreads();          // wb reused next tile
        t = tn;
    }

    // ---- last CTA decodes token ids ----
    __threadfence();
    __syncthreads();
    if (tid == 0) {
        int c = atomicAdd(&g_done, 1);
        is_last = (c == (int)gridDim.x - 1);
    }
    __syncthreads();
    if (is_last) {
        if (tid == 0) g_done = 0;
        __threadfence();
        if (tid < STEPS) {
            uint32_t idx = ~((uint32_t)(g_best[tid] & 0xffffffffu));
            out[(out_size - STEPS) + tid] = (float)idx;
        }
    }
#undef PREFETCH_TILE
}

// ============================================================================
extern "C" void kernel_launch(void* const* d_in, const int* in_sizes, int n_in,
                              void* d_out, int out_size) {
    const float* inp   = (const float*)d_in[0];
    const float* embed = (const float*)d_in[1];
    const float* w_ih  = (const float*)d_in[2];
    const float* w_hh  = (const float*)d_in[3];
    const float* b_ih  = (const float*)d_in[4];
    const float* b_hh  = (const float*)d_in[5];
    float* out = (float*)d_out;
    (void)in_sizes; (void)n_in;

    const int write_cs = (out_size >= STEPS * 128 + STEPS) ? 1 : 0;

    // Phase A: cluster-of-8 LSTM
    {
        cudaLaunchConfig_t cfg = {};
        cfg.gridDim  = dim3(8, 1, 1);
        cfg.blockDim = dim3(256, 1, 1);
        cfg.dynamicSmemBytes = 0;
        cfg.stream = 0;
        cudaLaunchAttribute attrs[1];
        attrs[0].id = cudaLaunchAttributeClusterDimension;
        attrs[0].val.clusterDim.x = 8;
        attrs[0].val.clusterDim.y = 1;
        attrs[0].val.clusterDim.z = 1;
        cfg.attrs = attrs;
        cfg.numAttrs = 1;
        cudaLaunchKernelEx(&cfg, k1_lstm, embed, w_ih, w_hh, inp, b_ih, b_hh,
                           out, write_cs);
    }

    // Phase B: persistent mma.sync scoring + argmax + decode
    k2_score<<<K2CTAS, 256>>>(embed, out, out_size);
}

// round 8
// speedup vs baseline: 1.9044x; 1.3459x over previous
#include <cuda_runtime.h>
#include <cuda_bf16.h>
#include <cstdint>
#include <cfloat>

#define VOCAB   500000
#define EMB_D   128
#define HID     128
#define STEPS   64
#define NTILES  3907          // ceil(VOCAB/128)
#define K2CTAS  148

// ---------------- device globals (scratch; no allocation allowed) ----------
__device__ float               g_cs[STEPS * HID];    // cell states [step][k]
__device__ unsigned long long  g_best[STEPS];        // (enc(score)<<32)|~idx
__device__ int                 g_done = 0;           // last-CTA counter (self-reset)

// ---------------- helpers ---------------------------------------------------
__device__ __forceinline__ uint32_t enc_f32(float f) {
    uint32_t u = __float_as_uint(f);
    return (u & 0x80000000u) ? ~u : (u | 0x80000000u);
}
__device__ __forceinline__ uint32_t smem_u32(const void* p) {
    return (uint32_t)__cvta_generic_to_shared(p);
}
__device__ __forceinline__ uint32_t mapa_rank(uint32_t local, uint32_t rank) {
    uint32_t r;
    asm volatile("mapa.shared::cluster.u32 %0, %1, %2;" : "=r"(r) : "r"(local), "r"(rank));
    return r;
}
__device__ __forceinline__ uint32_t my_cluster_rank() {
    uint32_t r; asm("mov.u32 %0, %%cluster_ctarank;" : "=r"(r)); return r;
}
__device__ __forceinline__ void cluster_sync_all() {
    asm volatile("barrier.cluster.arrive.aligned;" ::: "memory");
    asm volatile("barrier.cluster.wait.aligned;"   ::: "memory");
}
// fast activations (MUFU-based, ~1e-6 rel err; overflow-safe)
__device__ __forceinline__ float sig_fast(float x) {
    return __fdividef(1.0f, 1.0f + __expf(-x));
}
__device__ __forceinline__ float tanh_fast(float x) {
    return 1.0f - __fdividef(2.0f, __expf(2.0f * x) + 1.0f);
}

// split a float2 into bf16x2 hi and bf16x2 lo(residual)
__device__ __forceinline__ void split2(float2 v, uint32_t& hi, uint32_t& lo) {
    __nv_bfloat162 h = __floats2bfloat162_rn(v.x, v.y);
    hi = *(uint32_t*)&h;
    float rx = v.x - __bfloat162float(h.x);
    float ry = v.y - __bfloat162float(h.y);
    __nv_bfloat162 l = __floats2bfloat162_rn(rx, ry);
    lo = *(uint32_t*)&l;
}

// m16n8k16 row.col f32.bf16.bf16.f32
__device__ __forceinline__ void mma16816(float* c, const uint32_t* a,
                                         uint32_t b0, uint32_t b1) {
    asm volatile(
        "mma.sync.aligned.m16n8k16.row.col.f32.bf16.bf16.f32 "
        "{%0,%1,%2,%3}, {%4,%5,%6,%7}, {%8,%9}, {%0,%1,%2,%3};"
        : "+f"(c[0]), "+f"(c[1]), "+f"(c[2]), "+f"(c[3])
        : "r"(a[0]), "r"(a[1]), "r"(a[2]), "r"(a[3]), "r"(b0), "r"(b1));
}

// ============================================================================
// K1: 64 LSTM steps (cluster of 8 CTAs x 256 threads).
//     Handoff = HW barrier.cluster (UCGABAR path ~490cyc; beats mbarrier
//     remote-arrive by ~2000cyc/step empirically). 32 sender threads x 4
//     st.shared::cluster.b64 each; MUFU activations; 1 __syncthreads/step.
// ============================================================================
__global__ void __launch_bounds__(256, 1)
k1_lstm(const float* __restrict__ embed,
        const float* __restrict__ w_ih,
        const float* __restrict__ w_hh,
        const float* __restrict__ inp,
        const float* __restrict__ b_ih,
        const float* __restrict__ b_hh,
        float* __restrict__ out, int write_cs) {
    __shared__ float xh[2][256];
    __shared__ float gates_sm[64];
    __shared__ float Ksm[64];
    __shared__ float inp_sm[128];
    __shared__ alignas(8) float stage[32];          // [c x16 | h x16]

    const int tid  = threadIdx.x;
    const uint32_t rank = my_cluster_rank();

    const int lr   = tid >> 2;          // local gate row 0..63
    const int part = tid & 3;           // column quarter
    const int g    = lr >> 4;           // gate 0..3
    const int jj   = lr & 15;           // local hidden idx
    const int j    = (int)rank * 16 + jj;
    const int grow = g * 128 + j;       // global gate row

    if (rank == 0 && tid < STEPS) g_best[tid] = 0ull;

    if (tid < 128) {
        inp_sm[tid]      = inp[tid];
        xh[0][tid]       = embed[tid];
        xh[0][128 + tid] = 0.f;
    }

    float w[64];
    #pragma unroll
    for (int cc = 0; cc < 64; ++cc) {
        int col = part * 64 + cc;
        w[cc] = (col < 128) ? w_ih[grow * 256 + col]
                            : w_hh[grow * 128 + (col - 128)];
    }

    // hoisted sender addresses: thread tid<32 -> dest rank = tid>>2,
    // owns u64 pairs jj4..jj4+3 of the 16-u64 state block (0-7 = c, 8-15 = h)
    uint32_t rbase[2];
    int jj4 = (tid & 3) * 4;
    if (tid < 32) {
        uint32_t dr = (uint32_t)(tid >> 2);
        #pragma unroll
        for (int pn = 0; pn < 2; ++pn) {
            uint32_t base = (jj4 < 8)
                ? smem_u32(&xh[pn][(int)rank * 16]) + 8u * jj4
                : smem_u32(&xh[pn][128 + (int)rank * 16]) + 8u * (jj4 - 8);
            rbase[pn] = mapa_rank(base, dr);
        }
    }
    __syncthreads();

    // fold K[grow] = b_ih + b_hh + W_ih[:,128:] @ inp
    {
        const float* wr = w_ih + grow * 256 + 128 + part * 32;
        float s = 0.f;
        #pragma unroll 8
        for (int c = 0; c < 32; ++c) s = fmaf(wr[c], inp_sm[part * 32 + c], s);
        s += __shfl_xor_sync(0xffffffffu, s, 1);
        s += __shfl_xor_sync(0xffffffffu, s, 2);
        if (part == 0) Ksm[lr] = s + b_ih[grow] + b_hh[grow];
    }
    __syncthreads();

    float c_reg = 0.f, k0v = 0.f, k1v = 0.f, k2v = 0.f, k3v = 0.f;
    if (tid < 16) {
        k0v = Ksm[ 0 + tid]; k1v = Ksm[16 + tid];
        k2v = Ksm[32 + tid]; k3v = Ksm[48 + tid];
    }
    __syncthreads();
    cluster_sync_all();     // xh[0] initialized in every CTA

    for (int step = 0; step < STEPS; ++step) {
        const int p = step & 1;
        const float4* xv = (const float4*)&xh[p][part * 64];
        float a0 = 0.f, a1 = 0.f, a2 = 0.f, a3 = 0.f;
        #pragma unroll
        for (int qq = 0; qq < 16; ++qq) {
            float4 v = xv[qq];
            a0 = fmaf(w[4*qq + 0], v.x, a0);
            a1 = fmaf(w[4*qq + 1], v.y, a1);
            a2 = fmaf(w[4*qq + 2], v.z, a2);
            a3 = fmaf(w[4*qq + 3], v.w, a3);
        }
        float acc = (a0 + a1) + (a2 + a3);
        acc += __shfl_xor_sync(0xffffffffu, acc, 1);
        acc += __shfl_xor_sync(0xffffffffu, acc, 2);
        if (part == 0) gates_sm[lr] = acc;
        __syncthreads();          // the only block barrier per step

        if (tid < 32) {           // warp 0: epilogue + senders
            if (tid < 16) {
                int je = (int)rank * 16 + tid;
                float gi = gates_sm[ 0 + tid] + k0v;
                float gf = gates_sm[16 + tid] + k1v;
                float gg = gates_sm[32 + tid] + k2v;
                float go = gates_sm[48 + tid] + k3v;
                float iv = sig_fast(gi), fv = sig_fast(gf);
                float gv = tanh_fast(gg), ov = sig_fast(go);
                float c_new = fv * c_reg + iv * gv;
                float h_new = ov * tanh_fast(c_new);
                c_reg = c_new;
                if (write_cs) out[step * 128 + je] = c_new;
                g_cs[step * 128 + je] = c_new;
                stage[tid]      = c_new;
                stage[16 + tid] = h_new;
            }
            __syncwarp();
            if (step < STEPS - 1) {
                const unsigned long long* sg = (const unsigned long long*)stage;
                uint32_t rb = rbase[p ^ 1];
                #pragma unroll
                for (int i = 0; i < 4; ++i) {
                    asm volatile("st.shared::cluster.b64 [%0], %1;"
                                 :: "r"(rb + 8u * i), "l"(sg[jj4 + i]) : "memory");
                }
            }
        }
        // HW cluster barrier: releases warp0's remote stores, acquires peers'
        cluster_sync_all();
    }
}

// ============================================================================
// K2: persistent scorer. 148 CTAs x 256 threads; CTA b handles tiles
//     b, b+148, ... bf16 3-segment mma.sync (hi.hi + hi.lo + lo.hi).
//     Running per-thread argmax in registers across ALL tiles; single
//     reduction at the end (no per-tile shuffles/barriers/atomics).
// ============================================================================
__global__ void __launch_bounds__(256, 1)
k2_score(const float* __restrict__ embed, float* __restrict__ out, int out_size) {
    __shared__ uint4 sbfrag[2048];                  // [nc*8+kc][lane], 32KB
    __shared__ unsigned long long wb[8][STEPS];
    __shared__ int is_last;

    const int tid  = threadIdx.x;
    const int lane = tid & 31;
    const int w    = tid >> 5;
    const int q    = lane & 3;          // col-quad within fragment
    const int r4   = lane >> 2;         // fragment row 0..7

    // ---- build B fragments from g_cs into smem (once per CTA) ----
    {
        const float2* c2 = (const float2*)g_cs;
        #pragma unroll
        for (int it = 0; it < 8; ++it) {
            int idx  = tid + it * 256;
            int ln   = idx & 31;
            int kc   = (idx >> 5) & 7;
            int nc   = idx >> 8;
            int n    = nc * 8 + (ln >> 2);
            int qq   = ln & 3;
            float2 p01 = c2[n * 64 + kc * 8 + qq];
            float2 p23 = c2[n * 64 + kc * 8 + qq + 4];
            uint32_t h01, l01, h23, l23;
            split2(p01, h01, l01);
            split2(p23, h23, l23);
            sbfrag[idx] = make_uint4(h01, h23, l01, l23);
        }
    }
    __syncthreads();

    const float2* e2 = (const float2*)embed;
    float2 F[32];                       // raw A prefetch buffer (64 regs)

#define PREFETCH_TILE(TT) do {                                                 \
    int _r0 = (TT) * 128 + w * 16 + r4;                                        \
    int _r1 = _r0 + 8;                                                         \
    size_t _b0 = (size_t)((_r0 < VOCAB) ? _r0 : 0) * 64;                       \
    size_t _b1 = (size_t)((_r1 < VOCAB) ? _r1 : 0) * 64;                       \
    _Pragma("unroll")                                                          \
    for (int kc = 0; kc < 8; ++kc) {                                           \
        F[kc * 4 + 0] = e2[_b0 + kc * 8 + q];                                  \
        F[kc * 4 + 1] = e2[_b1 + kc * 8 + q];                                  \
        F[kc * 4 + 2] = e2[_b0 + kc * 8 + q + 4];                              \
        F[kc * 4 + 3] = e2[_b1 + kc * 8 + q + 4];                              \
    } } while (0)

    // running best per (nc,e) slot: slot = nc*2+e  <->  step = nc*8+2q+e
    float bs[16]; int br[16];
    #pragma unroll
    for (int i = 0; i < 16; ++i) { bs[i] = -FLT_MAX; br[i] = 0; }

    int t = blockIdx.x;
    if (t < NTILES) PREFETCH_TILE(t);

    while (t < NTILES) {
        const int  row0 = t * 128 + w * 16 + r4;
        const int  row1 = row0 + 8;
        const bool v0 = row0 < VOCAB, v1 = row1 < VOCAB;

        // ---- split current A + row ssq ----
        uint32_t aH[8][4], aL[8][4];
        float ssq0 = 0.f, ssq1 = 0.f;
        const float2 z2 = make_float2(0.f, 0.f);
        #pragma unroll
        for (int kc = 0; kc < 8; ++kc) {
            float2 f00 = v0 ? F[kc * 4 + 0] : z2;
            float2 f10 = v1 ? F[kc * 4 + 1] : z2;
            float2 f01 = v0 ? F[kc * 4 + 2] : z2;
            float2 f11 = v1 ? F[kc * 4 + 3] : z2;
            ssq0 = fmaf(f00.x, f00.x, fmaf(f00.y, f00.y,
                    fmaf(f01.x, f01.x, fmaf(f01.y, f01.y, ssq0))));
            ssq1 = fmaf(f10.x, f10.x, fmaf(f10.y, f10.y,
                    fmaf(f11.x, f11.x, fmaf(f11.y, f11.y, ssq1))));
            split2(f00, aH[kc][0], aL[kc][0]);
            split2(f10, aH[kc][1], aL[kc][1]);
            split2(f01, aH[kc][2], aL[kc][2]);
            split2(f11, aH[kc][3], aL[kc][3]);
        }
        ssq0 += __shfl_xor_sync(0xffffffffu, ssq0, 1);
        ssq0 += __shfl_xor_sync(0xffffffffu, ssq0, 2);
        ssq1 += __shfl_xor_sync(0xffffffffu, ssq1, 1);
        ssq1 += __shfl_xor_sync(0xffffffffu, ssq1, 2);
        const float iv0 = 1.0f / fmaxf(sqrtf(ssq0), 1e-8f);
        const float iv1 = 1.0f / fmaxf(sqrtf(ssq1), 1e-8f);

        // ---- prefetch next tile (LDGs overlap the MMA loop below) ----
        const int tn = t + K2CTAS;
        if (tn < NTILES) PREFETCH_TILE(tn);

        // ---- MMA + per-nc running argmax (register-only epilogue) ----
        #pragma unroll
        for (int nc = 0; nc < 8; ++nc) {
            float c1[4]  = {0.f, 0.f, 0.f, 0.f};
            float c2a[4] = {0.f, 0.f, 0.f, 0.f};
            float c3[4]  = {0.f, 0.f, 0.f, 0.f};
            #pragma unroll
            for (int kc = 0; kc < 8; ++kc) {
                uint4 bb = sbfrag[(nc * 8 + kc) * 32 + lane];
                mma16816(c1,  aH[kc], bb.x, bb.y);   // hi*hi
                mma16816(c2a, aH[kc], bb.z, bb.w);   // hi*lo
                mma16816(c3,  aL[kc], bb.x, bb.y);   // lo*hi
            }
            #pragma unroll
            for (int e = 0; e < 2; ++e) {
                const int sl = nc * 2 + e;
                float s0 = v0 ? (c1[e]     + c2a[e]     + c3[e])     * iv0 : -FLT_MAX;
                float s1 = v1 ? (c1[2 + e] + c2a[2 + e] + c3[2 + e]) * iv1 : -FLT_MAX;
                if (s0 > bs[sl]) { bs[sl] = s0; br[sl] = row0; }  // row0 first:
                if (s1 > bs[sl]) { bs[sl] = s1; br[sl] = row1; }  // first-max wins
            }
        }
        t = tn;        // no barrier: warps free-run across tiles
    }

    // ---- single final reduction ----
    #pragma unroll
    for (int sl = 0; sl < 16; ++sl) {
        unsigned long long key =
            ((unsigned long long)enc_f32(bs[sl]) << 32) |
            (uint32_t)(~(uint32_t)br[sl]);
        #pragma unroll
        for (int off = 4; off < 32; off <<= 1) {
            unsigned long long o = __shfl_xor_sync(0xffffffffu, key, off);
            if (o > key) key = o;
        }
        if (r4 == 0) wb[w][(sl >> 1) * 8 + 2 * q + (sl & 1)] = key;
    }
    __syncthreads();
    if (tid < STEPS) {
        unsigned long long best = wb[0][tid];
        #pragma unroll
        for (int ww = 1; ww < 8; ++ww)
            if (wb[ww][tid] > best) best = wb[ww][tid];
        atomicMax(&g_best[tid], best);
    }

    // ---- last CTA decodes token ids ----
    __threadfence();
    __syncthreads();
    if (tid == 0) {
        int c = atomicAdd(&g_done, 1);
        is_last = (c == (int)gridDim.x - 1);
    }
    __syncthreads();
    if (is_last) {
        if (tid == 0) g_done = 0;
        __threadfence();
        if (tid < STEPS) {
            uint32_t idx = ~((uint32_t)(g_best[tid] & 0xffffffffu));
            out[(out_size - STEPS) + tid] = (float)idx;
        }
    }
#undef PREFETCH_TILE
}

// ============================================================================
extern "C" void kernel_launch(void* const* d_in, const int* in_sizes, int n_in,
                              void* d_out, int out_size) {
    const float* inp   = (const float*)d_in[0];
    const float* embed = (const float*)d_in[1];
    const float* w_ih  = (const float*)d_in[2];
    const float* w_hh  = (const float*)d_in[3];
    const float* b_ih  = (const float*)d_in[4];
    const float* b_hh  = (const float*)d_in[5];
    float* out = (float*)d_out;
    (void)in_sizes; (void)n_in;

    const int write_cs = (out_size >= STEPS * 128 + STEPS) ? 1 : 0;

    // Phase A: cluster-of-8 LSTM
    {
        cudaLaunchConfig_t cfg = {};
        cfg.gridDim  = dim3(8, 1, 1);
        cfg.blockDim = dim3(256, 1, 1);
        cfg.dynamicSmemBytes = 0;
        cfg.stream = 0;
        cudaLaunchAttribute attrs[1];
        attrs[0].id = cudaLaunchAttributeClusterDimension;
        attrs[0].val.clusterDim.x = 8;
        attrs[0].val.clusterDim.y = 1;
        attrs[0].val.clusterDim.z = 1;
        cfg.attrs = attrs;
        cfg.numAttrs = 1;
        cudaLaunchKernelEx(&cfg, k1_lstm, embed, w_ih, w_hh, inp, b_ih, b_hh,
                           out, write_cs);
    }

    // Phase B: persistent mma.sync scoring + argmax + decode
    k2_score<<<K2CTAS, 256>>>(embed, out, out_size);
}